// round 1
// baseline (speedup 1.0000x reference)
#include <cuda_runtime.h>

#define N_NODES 50000
#define N_EDGES 800000
#define HID 128
#define EIN 280           // 24 + 128 + 128
#define TE 64             // edges / nodes per CTA
#define XS 284            // xs row stride (pad for banks, %4==0)
#define HS 132            // h1s row stride
#define YS 260            // ys row stride (node kernel, 256+4)

typedef unsigned long long ull;

// scratch: segment-sum accumulator (no allocations allowed -> device global)
__device__ float4 g_mi4[N_NODES * (HID / 4)];

__device__ __forceinline__ ull pack2(float lo, float hi) {
    ull r; asm("mov.b64 %0, {%1, %2};" : "=l"(r) : "f"(lo), "f"(hi)); return r;
}
__device__ __forceinline__ float2 unpack2(ull v) {
    float2 r; asm("mov.b64 {%0, %1}, %2;" : "=f"(r.x), "=f"(r.y) : "l"(v)); return r;
}
__device__ __forceinline__ ull fma2(ull a, ull b, ull c) {
    ull d; asm("fma.rn.f32x2 %0, %1, %2, %3;" : "=l"(d) : "l"(a), "l"(b), "l"(c)); return d;
}

__global__ void zero_mi_kernel() {
    int i = blockIdx.x * blockDim.x + threadIdx.x;
    g_mi4[i] = make_float4(0.f, 0.f, 0.f, 0.f);
}

// ============================================================================
// Edge kernel: mij = relu(relu(x W1 + b1) W2 + b2); e = sigmoid(mij Wg + bg);
// atomic scatter mi[dst] += mij * e.   64 edges per CTA, 256 threads.
// Thread (ty,tx): 4 edges (ty*4..) x 8 cols (tx*8..), f32x2-packed over col pairs.
// ============================================================================
extern "C" __global__ void __launch_bounds__(256)
edge_kernel(const float* __restrict__ h, const int* __restrict__ ei,
            const float* __restrict__ ea,
            const float* __restrict__ W1, const float* __restrict__ b1,
            const float* __restrict__ W2, const float* __restrict__ b2,
            const float* __restrict__ Wg, const float* __restrict__ bg)
{
    extern __shared__ float smem[];
    float* xs  = smem;              // TE * XS
    float* h1s = xs + TE * XS;      // TE * HS
    float* ws  = h1s + TE * HS;     // 16 * 128
    __shared__ int dsts[TE];
    __shared__ int srcs[TE];

    const int tid = threadIdx.x;
    const int e0  = blockIdx.x * TE;

    // ---- gather ----
    if (tid < TE) {
        dsts[tid] = ei[e0 + tid];
        srcs[tid] = ei[N_EDGES + e0 + tid];
    }
    {
        const float4* ea4 = (const float4*)ea;
        for (int i = tid; i < TE * 6; i += 256) {
            int e = i / 6, j = i % 6;
            *(float4*)&xs[e * XS + j * 4] = ea4[(e0 + e) * 6 + j];
        }
    }
    __syncthreads();
    {
        const float4* h4 = (const float4*)h;
        for (int i = tid; i < TE * 32; i += 256) {
            int e = i >> 5, j = i & 31;
            *(float4*)&xs[e * XS + 24  + j * 4] = h4[dsts[e] * 32 + j];
            *(float4*)&xs[e * XS + 152 + j * 4] = h4[srcs[e] * 32 + j];
        }
    }

    const int ty = tid >> 4, tx = tid & 15;
    const int er = ty * 4, cc = tx * 8;

    // ---- layer 1: [TE x 280] @ [280 x 128] ----
    ull acc[4][4];
#pragma unroll
    for (int e = 0; e < 4; e++)
#pragma unroll
        for (int c = 0; c < 4; c++) acc[e][c] = 0ULL;

    for (int kt = 0; kt < EIN; kt += 8) {
        __syncthreads();
        {
            int r = tid >> 5, c4 = (tid & 31) << 2;
            *(float4*)&ws[r * 128 + c4] = *(const float4*)&W1[(kt + r) * 128 + c4];
        }
        __syncthreads();
#pragma unroll
        for (int k = 0; k < 8; ++k) {
            const ull* wp = (const ull*)&ws[k * 128 + cc];
            ull w0 = wp[0], w1 = wp[1], w2 = wp[2], w3 = wp[3];
#pragma unroll
            for (int e = 0; e < 4; ++e) {
                float xv = xs[(er + e) * XS + kt + k];
                ull xd = pack2(xv, xv);
                acc[e][0] = fma2(xd, w0, acc[e][0]);
                acc[e][1] = fma2(xd, w1, acc[e][1]);
                acc[e][2] = fma2(xd, w2, acc[e][2]);
                acc[e][3] = fma2(xd, w3, acc[e][3]);
            }
        }
    }
    {
        float4 bA = *(const float4*)&b1[cc];
        float4 bB = *(const float4*)&b1[cc + 4];
#pragma unroll
        for (int e = 0; e < 4; e++) {
            float2 p0 = unpack2(acc[e][0]), p1 = unpack2(acc[e][1]);
            float2 p2 = unpack2(acc[e][2]), p3 = unpack2(acc[e][3]);
            float4 o0 = make_float4(fmaxf(p0.x + bA.x, 0.f), fmaxf(p0.y + bA.y, 0.f),
                                    fmaxf(p1.x + bA.z, 0.f), fmaxf(p1.y + bA.w, 0.f));
            float4 o1 = make_float4(fmaxf(p2.x + bB.x, 0.f), fmaxf(p2.y + bB.y, 0.f),
                                    fmaxf(p3.x + bB.z, 0.f), fmaxf(p3.y + bB.w, 0.f));
            *(float4*)&h1s[(er + e) * HS + cc]     = o0;
            *(float4*)&h1s[(er + e) * HS + cc + 4] = o1;
        }
    }

    // ---- layer 2: [TE x 128] @ [128 x 128] ----
    ull acc2[4][4];
#pragma unroll
    for (int e = 0; e < 4; e++)
#pragma unroll
        for (int c = 0; c < 4; c++) acc2[e][c] = 0ULL;

    for (int kt = 0; kt < HID; kt += 16) {
        __syncthreads();
        {
            int r = tid >> 4, c8 = (tid & 15) * 8;
            *(float4*)&ws[r * 128 + c8]     = *(const float4*)&W2[(kt + r) * 128 + c8];
            *(float4*)&ws[r * 128 + c8 + 4] = *(const float4*)&W2[(kt + r) * 128 + c8 + 4];
        }
        __syncthreads();
#pragma unroll
        for (int k = 0; k < 16; ++k) {
            const ull* wp = (const ull*)&ws[k * 128 + cc];
            ull w0 = wp[0], w1 = wp[1], w2 = wp[2], w3 = wp[3];
#pragma unroll
            for (int e = 0; e < 4; ++e) {
                float xv = h1s[(er + e) * HS + kt + k];
                ull xd = pack2(xv, xv);
                acc2[e][0] = fma2(xd, w0, acc2[e][0]);
                acc2[e][1] = fma2(xd, w1, acc2[e][1]);
                acc2[e][2] = fma2(xd, w2, acc2[e][2]);
                acc2[e][3] = fma2(xd, w3, acc2[e][3]);
            }
        }
    }

    // ---- gate + scatter ----
    {
        float4 bA = *(const float4*)&b2[cc];
        float4 bB = *(const float4*)&b2[cc + 4];
        float4 gA = *(const float4*)&Wg[cc];
        float4 gB = *(const float4*)&Wg[cc + 4];
        float bgv = bg[0];
        float* g_mi = (float*)g_mi4;
#pragma unroll
        for (int e = 0; e < 4; e++) {
            float2 p0 = unpack2(acc2[e][0]), p1 = unpack2(acc2[e][1]);
            float2 p2 = unpack2(acc2[e][2]), p3 = unpack2(acc2[e][3]);
            float m0 = fmaxf(p0.x + bA.x, 0.f), m1 = fmaxf(p0.y + bA.y, 0.f);
            float m2 = fmaxf(p1.x + bA.z, 0.f), m3 = fmaxf(p1.y + bA.w, 0.f);
            float m4 = fmaxf(p2.x + bB.x, 0.f), m5 = fmaxf(p2.y + bB.y, 0.f);
            float m6 = fmaxf(p3.x + bB.z, 0.f), m7 = fmaxf(p3.y + bB.w, 0.f);
            float part = m0 * gA.x + m1 * gA.y + m2 * gA.z + m3 * gA.w
                       + m4 * gB.x + m5 * gB.y + m6 * gB.z + m7 * gB.w;
#pragma unroll
            for (int off = 8; off >= 1; off >>= 1)
                part += __shfl_xor_sync(0xffffffffu, part, off);
            float g = 1.f / (1.f + expf(-(part + bgv)));
            int d = dsts[er + e];
            float4 v0 = make_float4(m0 * g, m1 * g, m2 * g, m3 * g);
            float4 v1 = make_float4(m4 * g, m5 * g, m6 * g, m7 * g);
            atomicAdd((float4*)&g_mi[d * HID + cc],     v0);
            atomicAdd((float4*)&g_mi[d * HID + cc + 4], v1);
        }
    }
}

// ============================================================================
// Node kernel: out = relu([mi, h] Wn1 + bn1) Wn2 + bn2.   64 nodes per CTA.
// ============================================================================
extern "C" __global__ void __launch_bounds__(256)
node_kernel(const float* __restrict__ h,
            const float* __restrict__ Wn1, const float* __restrict__ bn1,
            const float* __restrict__ Wn2, const float* __restrict__ bn2,
            float* __restrict__ out)
{
    extern __shared__ float smem[];
    float* ys  = smem;              // TE * YS
    float* h1s = ys + TE * YS;      // TE * HS
    float* ws  = h1s + TE * HS;     // 16 * 128

    const int tid = threadIdx.x;
    const int n0  = blockIdx.x * TE;

    // ---- gather [mi | h] ----
    {
        const float4* h4 = (const float4*)h;
        const float4* m4 = (const float4*)g_mi4;
        for (int i = tid; i < TE * 64; i += 256) {
            int n = i >> 6, j = i & 63;
            int gn = n0 + n;
            float4 v = make_float4(0.f, 0.f, 0.f, 0.f);
            int off;
            if (j < 32) { if (gn < N_NODES) v = m4[gn * 32 + j]; off = j * 4; }
            else        { if (gn < N_NODES) v = h4[gn * 32 + (j - 32)]; off = 128 + (j - 32) * 4; }
            *(float4*)&ys[n * YS + off] = v;
        }
    }

    const int ty = tid >> 4, tx = tid & 15;
    const int er = ty * 4, cc = tx * 8;

    // ---- layer 1: [TE x 256] @ [256 x 128], relu ----
    ull acc[4][4];
#pragma unroll
    for (int e = 0; e < 4; e++)
#pragma unroll
        for (int c = 0; c < 4; c++) acc[e][c] = 0ULL;

    for (int kt = 0; kt < 2 * HID; kt += 16) {
        __syncthreads();
        {
            int r = tid >> 4, c8 = (tid & 15) * 8;
            *(float4*)&ws[r * 128 + c8]     = *(const float4*)&Wn1[(kt + r) * 128 + c8];
            *(float4*)&ws[r * 128 + c8 + 4] = *(const float4*)&Wn1[(kt + r) * 128 + c8 + 4];
        }
        __syncthreads();
#pragma unroll
        for (int k = 0; k < 16; ++k) {
            const ull* wp = (const ull*)&ws[k * 128 + cc];
            ull w0 = wp[0], w1 = wp[1], w2 = wp[2], w3 = wp[3];
#pragma unroll
            for (int e = 0; e < 4; ++e) {
                float xv = ys[(er + e) * YS + kt + k];
                ull xd = pack2(xv, xv);
                acc[e][0] = fma2(xd, w0, acc[e][0]);
                acc[e][1] = fma2(xd, w1, acc[e][1]);
                acc[e][2] = fma2(xd, w2, acc[e][2]);
                acc[e][3] = fma2(xd, w3, acc[e][3]);
            }
        }
    }
    {
        float4 bA = *(const float4*)&bn1[cc];
        float4 bB = *(const float4*)&bn1[cc + 4];
#pragma unroll
        for (int e = 0; e < 4; e++) {
            float2 p0 = unpack2(acc[e][0]), p1 = unpack2(acc[e][1]);
            float2 p2 = unpack2(acc[e][2]), p3 = unpack2(acc[e][3]);
            float4 o0 = make_float4(fmaxf(p0.x + bA.x, 0.f), fmaxf(p0.y + bA.y, 0.f),
                                    fmaxf(p1.x + bA.z, 0.f), fmaxf(p1.y + bA.w, 0.f));
            float4 o1 = make_float4(fmaxf(p2.x + bB.x, 0.f), fmaxf(p2.y + bB.y, 0.f),
                                    fmaxf(p3.x + bB.z, 0.f), fmaxf(p3.y + bB.w, 0.f));
            *(float4*)&h1s[(er + e) * HS + cc]     = o0;
            *(float4*)&h1s[(er + e) * HS + cc + 4] = o1;
        }
    }

    // ---- layer 2: [TE x 128] @ [128 x 128], no relu ----
    ull acc2[4][4];
#pragma unroll
    for (int e = 0; e < 4; e++)
#pragma unroll
        for (int c = 0; c < 4; c++) acc2[e][c] = 0ULL;

    for (int kt = 0; kt < HID; kt += 16) {
        __syncthreads();
        {
            int r = tid >> 4, c8 = (tid & 15) * 8;
            *(float4*)&ws[r * 128 + c8]     = *(const float4*)&Wn2[(kt + r) * 128 + c8];
            *(float4*)&ws[r * 128 + c8 + 4] = *(const float4*)&Wn2[(kt + r) * 128 + c8 + 4];
        }
        __syncthreads();
#pragma unroll
        for (int k = 0; k < 16; ++k) {
            const ull* wp = (const ull*)&ws[k * 128 + cc];
            ull w0 = wp[0], w1 = wp[1], w2 = wp[2], w3 = wp[3];
#pragma unroll
            for (int e = 0; e < 4; ++e) {
                float xv = h1s[(er + e) * HS + kt + k];
                ull xd = pack2(xv, xv);
                acc2[e][0] = fma2(xd, w0, acc2[e][0]);
                acc2[e][1] = fma2(xd, w1, acc2[e][1]);
                acc2[e][2] = fma2(xd, w2, acc2[e][2]);
                acc2[e][3] = fma2(xd, w3, acc2[e][3]);
            }
        }
    }
    {
        float4 bA = *(const float4*)&bn2[cc];
        float4 bB = *(const float4*)&bn2[cc + 4];
#pragma unroll
        for (int e = 0; e < 4; e++) {
            int gn = n0 + er + e;
            if (gn >= N_NODES) continue;
            float2 p0 = unpack2(acc2[e][0]), p1 = unpack2(acc2[e][1]);
            float2 p2 = unpack2(acc2[e][2]), p3 = unpack2(acc2[e][3]);
            float4 o0 = make_float4(p0.x + bA.x, p0.y + bA.y, p1.x + bA.z, p1.y + bA.w);
            float4 o1 = make_float4(p2.x + bB.x, p2.y + bB.y, p3.x + bB.z, p3.y + bB.w);
            *(float4*)&out[gn * HID + cc]     = o0;
            *(float4*)&out[gn * HID + cc + 4] = o1;
        }
    }
}

extern "C" void kernel_launch(void* const* d_in, const int* in_sizes, int n_in,
                              void* d_out, int out_size)
{
    const float* h   = (const float*)d_in[0];
    const int*   ei  = (const int*)d_in[1];
    const float* ea  = (const float*)d_in[2];
    const float* W1  = (const float*)d_in[3];
    const float* b1  = (const float*)d_in[4];
    const float* W2  = (const float*)d_in[5];
    const float* b2  = (const float*)d_in[6];
    const float* Wg  = (const float*)d_in[7];
    const float* bg  = (const float*)d_in[8];
    const float* Wn1 = (const float*)d_in[9];
    const float* bn1 = (const float*)d_in[10];
    const float* Wn2 = (const float*)d_in[11];
    const float* bn2 = (const float*)d_in[12];
    float* out = (float*)d_out;

    size_t smem_e = (size_t)(TE * XS + TE * HS + 16 * 128) * sizeof(float);
    size_t smem_n = (size_t)(TE * YS + TE * HS + 16 * 128) * sizeof(float);
    cudaFuncSetAttribute(edge_kernel, cudaFuncAttributeMaxDynamicSharedMemorySize, (int)smem_e);
    cudaFuncSetAttribute(node_kernel, cudaFuncAttributeMaxDynamicSharedMemorySize, (int)smem_n);

    zero_mi_kernel<<<(N_NODES * (HID / 4)) / 512, 512>>>();
    edge_kernel<<<N_EDGES / TE, 256, smem_e>>>(h, ei, ea, W1, b1, W2, b2, Wg, bg);
    node_kernel<<<(N_NODES + TE - 1) / TE, 256, smem_n>>>(h, Wn1, bn1, Wn2, bn2, out);
}

// round 3
// speedup vs baseline: 2.7609x; 2.7609x over previous
#include <cuda_runtime.h>
#include <cuda_bf16.h>
#include <cstdint>

#define N_NODES 50000
#define N_EDGES 800000
#define HID 128

typedef unsigned long long ull;

// ---------------- device-global scratch (no allocations allowed) ----------------
__device__ float4 g_mi4[N_NODES * (HID / 4)];
__device__ float g_P[N_NODES * HID];          // h @ We1[24:152]
__device__ float g_Q[N_NODES * HID];          // h @ We1[152:280]
__device__ uint32_t g_w1f_hi[128 * 16];       // We1[0:24] B-fragments (K padded to 32)
__device__ uint32_t g_w1f_lo[128 * 16];
__device__ uint32_t g_w2f_hi[128 * 64];       // We2 B-fragments
__device__ uint32_t g_w2f_lo[128 * 64];

// ---------------- helpers ----------------
__device__ __forceinline__ void split_pack(float v0, float v1, uint32_t& hi, uint32_t& lo) {
    __nv_bfloat162 h2 = __floats2bfloat162_rn(v0, v1);
    float r0 = v0 - __bfloat162float(h2.x);
    float r1 = v1 - __bfloat162float(h2.y);
    __nv_bfloat162 l2 = __floats2bfloat162_rn(r0, r1);
    hi = *reinterpret_cast<uint32_t*>(&h2);
    lo = *reinterpret_cast<uint32_t*>(&l2);
}

__device__ __forceinline__ void mma_bf16(float* d, const uint32_t* a, const uint32_t* b) {
    asm volatile("mma.sync.aligned.m16n8k16.row.col.f32.bf16.bf16.f32 "
        "{%0,%1,%2,%3}, {%4,%5,%6,%7}, {%8,%9}, {%0,%1,%2,%3};"
        : "+f"(d[0]), "+f"(d[1]), "+f"(d[2]), "+f"(d[3])
        : "r"(a[0]), "r"(a[1]), "r"(a[2]), "r"(a[3]), "r"(b[0]), "r"(b[1]));
}

__device__ __forceinline__ ull pack2(float lo, float hi) {
    ull r; asm("mov.b64 %0, {%1, %2};" : "=l"(r) : "f"(lo), "f"(hi)); return r;
}
__device__ __forceinline__ float2 unpack2(ull v) {
    float2 r; asm("mov.b64 {%0, %1}, %2;" : "=f"(r.x), "=f"(r.y) : "l"(v)); return r;
}
__device__ __forceinline__ ull fma2(ull a, ull b, ull c) {
    ull d; asm("fma.rn.f32x2 %0, %1, %2, %3;" : "=l"(d) : "l"(a), "l"(b), "l"(c)); return d;
}

// ---------------- small kernels ----------------
__global__ void zero_mi_kernel() {
    int i = blockIdx.x * blockDim.x + threadIdx.x;
    g_mi4[i] = make_float4(0.f, 0.f, 0.f, 0.f);
}

__global__ void prep_frag_kernel(const float* __restrict__ W1, const float* __restrict__ W2) {
    int i = blockIdx.x * blockDim.x + threadIdx.x;
    if (i < 2048) {
        int n = i >> 4, kp = i & 15;
        int k0 = kp * 2;
        float v0 = (k0 < 24) ? W1[k0 * 128 + n] : 0.f;
        float v1 = (k0 + 1 < 24) ? W1[(k0 + 1) * 128 + n] : 0.f;
        uint32_t hi, lo; split_pack(v0, v1, hi, lo);
        g_w1f_hi[i] = hi; g_w1f_lo[i] = lo;
    } else if (i < 2048 + 8192) {
        int t = i - 2048;
        int n = t >> 6, kp = t & 63;
        float v0 = W2[(kp * 2) * 128 + n];
        float v1 = W2[(kp * 2 + 1) * 128 + n];
        uint32_t hi, lo; split_pack(v0, v1, hi, lo);
        g_w2f_hi[t] = hi; g_w2f_lo[t] = lo;
    }
}

// ---------------- P/Q precompute: P = h @ We1[24:152], Q = h @ We1[152:280] ----------------
extern "C" __global__ void __launch_bounds__(256)
pq_kernel(const float* __restrict__ h, const float* __restrict__ We1) {
    __shared__ float ys[64 * 132];
    __shared__ float ws[16 * 128];
    const int tid = threadIdx.x;
    const int n0 = blockIdx.x * 64;
    const float* W = We1 + (24 + blockIdx.y * 128) * 128;
    float* Pout = (blockIdx.y == 0) ? g_P : g_Q;

    {
        const float4* h4 = (const float4*)h;
        for (int i = tid; i < 64 * 32; i += 256) {
            int n = i >> 5, j = i & 31;
            int gn = n0 + n;
            float4 v = make_float4(0.f, 0.f, 0.f, 0.f);
            if (gn < N_NODES) v = h4[gn * 32 + j];
            *(float4*)&ys[n * 132 + j * 4] = v;
        }
    }

    const int ty = tid >> 4, tx = tid & 15;
    const int er = ty * 4, cc = tx * 8;

    ull acc[4][4];
#pragma unroll
    for (int e = 0; e < 4; e++)
#pragma unroll
        for (int c = 0; c < 4; c++) acc[e][c] = 0ULL;

    for (int kt = 0; kt < 128; kt += 16) {
        __syncthreads();
        {
            int r = tid >> 4, c8 = (tid & 15) * 8;
            *(float4*)&ws[r * 128 + c8]     = *(const float4*)&W[(kt + r) * 128 + c8];
            *(float4*)&ws[r * 128 + c8 + 4] = *(const float4*)&W[(kt + r) * 128 + c8 + 4];
        }
        __syncthreads();
#pragma unroll
        for (int k = 0; k < 16; ++k) {
            const ull* wp = (const ull*)&ws[k * 128 + cc];
            ull w0 = wp[0], w1 = wp[1], w2 = wp[2], w3 = wp[3];
#pragma unroll
            for (int e = 0; e < 4; ++e) {
                float xv = ys[(er + e) * 132 + kt + k];
                ull xd = pack2(xv, xv);
                acc[e][0] = fma2(xd, w0, acc[e][0]);
                acc[e][1] = fma2(xd, w1, acc[e][1]);
                acc[e][2] = fma2(xd, w2, acc[e][2]);
                acc[e][3] = fma2(xd, w3, acc[e][3]);
            }
        }
    }
#pragma unroll
    for (int e = 0; e < 4; e++) {
        int gn = n0 + er + e;
        if (gn >= N_NODES) continue;
        float2 p0 = unpack2(acc[e][0]), p1 = unpack2(acc[e][1]);
        float2 p2 = unpack2(acc[e][2]), p3 = unpack2(acc[e][3]);
        *(float4*)&Pout[gn * 128 + cc]     = make_float4(p0.x, p0.y, p1.x, p1.y);
        *(float4*)&Pout[gn * 128 + cc + 4] = make_float4(p2.x, p2.y, p3.x, p3.y);
    }
}

// ---------------- edge kernel ----------------
// smem: eas [128][24] @0 (12288B); a2hi [128][68] @12288 (34816B); a2lo @47104 (34816B);
//       h1f [128][132] fp32 overlays @0 (67584B, written after phase2 mma + sync);
//       dsts @81920, srcs @82432, gsm @82944; total 83456B.
#define SMEM_EDGE 83456

extern "C" __global__ void __launch_bounds__(256, 2)
edge_kernel(const int* __restrict__ ei, const float* __restrict__ ea,
            const float* __restrict__ b1, const float* __restrict__ b2,
            const float* __restrict__ Wg, const float* __restrict__ bg)
{
    extern __shared__ __align__(16) char sm[];
    float*    eas  = (float*)sm;
    uint32_t* a2hi = (uint32_t*)(sm + 12288);
    uint32_t* a2lo = (uint32_t*)(sm + 47104);
    float*    h1f  = (float*)sm;
    int*      dsts = (int*)(sm + 81920);
    int*      srcs = (int*)(sm + 82432);
    float*    gsm  = (float*)(sm + 82944);

    const int tid = threadIdx.x;
    const int wid = tid >> 5, lane = tid & 31;
    const int g = lane >> 2, q = lane & 3;
    const int wm = wid & 3, wn = wid >> 2;
    const int e0 = blockIdx.x * 128;

    if (tid < 128) {
        dsts[tid] = ei[e0 + tid];
        srcs[tid] = ei[N_EDGES + e0 + tid];
        gsm[tid] = 0.f;
    }
    {
        const float4* ea4 = (const float4*)ea;
        for (int i = tid; i < 128 * 6; i += 256) {
            int e = i / 6, j = i % 6;
            *(float4*)&eas[e * 24 + j * 4] = ea4[(e0 + e) * 6 + j];
        }
    }
    __syncthreads();

    float acc[2][8][4];
#pragma unroll
    for (int mt = 0; mt < 2; mt++)
#pragma unroll
        for (int nt = 0; nt < 8; nt++)
#pragma unroll
            for (int x = 0; x < 4; x++) acc[mt][nt][x] = 0.f;

    // ===== phase 1: ea @ W1a (K=24 padded to 32), bf16 3-term split =====
#pragma unroll
    for (int ks = 0; ks < 2; ks++) {
        uint32_t Ah[2][4], Al[2][4];
#pragma unroll
        for (int mt = 0; mt < 2; mt++) {
            int r = wm * 32 + mt * 16 + g;
            int k0 = ks * 16 + q * 2;
            int k8 = k0 + 8;
            float v00 = eas[r * 24 + k0];            // k0 < 24 always
            float v01 = eas[r * 24 + k0 + 1];
            split_pack(v00, v01, Ah[mt][0], Al[mt][0]);
            float v10 = eas[(r + 8) * 24 + k0];
            float v11 = eas[(r + 8) * 24 + k0 + 1];
            split_pack(v10, v11, Ah[mt][1], Al[mt][1]);
            float v20 = (k8 < 24) ? eas[r * 24 + k8] : 0.f;
            float v21 = (k8 < 24) ? eas[r * 24 + k8 + 1] : 0.f;
            split_pack(v20, v21, Ah[mt][2], Al[mt][2]);
            float v30 = (k8 < 24) ? eas[(r + 8) * 24 + k8] : 0.f;
            float v31 = (k8 < 24) ? eas[(r + 8) * 24 + k8 + 1] : 0.f;
            split_pack(v30, v31, Ah[mt][3], Al[mt][3]);
        }
#pragma unroll
        for (int nt = 0; nt < 8; nt++) {
            int n = wn * 64 + nt * 8 + g;
            uint32_t bh[2], bl[2];
            bh[0] = g_w1f_hi[n * 16 + ks * 8 + q];
            bh[1] = g_w1f_hi[n * 16 + ks * 8 + 4 + q];
            bl[0] = g_w1f_lo[n * 16 + ks * 8 + q];
            bl[1] = g_w1f_lo[n * 16 + ks * 8 + 4 + q];
#pragma unroll
            for (int mt = 0; mt < 2; mt++) {
                mma_bf16(acc[mt][nt], Ah[mt], bh);
                mma_bf16(acc[mt][nt], Al[mt], bh);
                mma_bf16(acc[mt][nt], Ah[mt], bl);
            }
        }
    }

    // ===== epilogue 1: + P[dst] + Q[src] + b1, relu, split -> smem A2 =====
#pragma unroll
    for (int mt = 0; mt < 2; mt++)
#pragma unroll
    for (int nt = 0; nt < 8; nt++) {
        int r = wm * 32 + mt * 16 + g;
        int c = wn * 64 + nt * 8 + q * 2;
        int cp = c >> 1;
        float2 b1v = __ldg((const float2*)&b1[c]);
        {
            int d = dsts[r], s = srcs[r];
            float2 pv = __ldg((const float2*)&g_P[d * 128 + c]);
            float2 qv = __ldg((const float2*)&g_Q[s * 128 + c]);
            float t0 = fmaxf(acc[mt][nt][0] + pv.x + qv.x + b1v.x, 0.f);
            float t1 = fmaxf(acc[mt][nt][1] + pv.y + qv.y + b1v.y, 0.f);
            uint32_t hi, lo; split_pack(t0, t1, hi, lo);
            a2hi[r * 68 + cp] = hi; a2lo[r * 68 + cp] = lo;
        }
        {
            int r8 = r + 8;
            int d = dsts[r8], s = srcs[r8];
            float2 pv = __ldg((const float2*)&g_P[d * 128 + c]);
            float2 qv = __ldg((const float2*)&g_Q[s * 128 + c]);
            float t0 = fmaxf(acc[mt][nt][2] + pv.x + qv.x + b1v.x, 0.f);
            float t1 = fmaxf(acc[mt][nt][3] + pv.y + qv.y + b1v.y, 0.f);
            uint32_t hi, lo; split_pack(t0, t1, hi, lo);
            a2hi[r8 * 68 + cp] = hi; a2lo[r8 * 68 + cp] = lo;
        }
    }
    __syncthreads();

    // ===== phase 2: layer2 [128x128] @ [128x128], bf16 3-term split =====
#pragma unroll
    for (int mt = 0; mt < 2; mt++)
#pragma unroll
        for (int nt = 0; nt < 8; nt++)
#pragma unroll
            for (int x = 0; x < 4; x++) acc[mt][nt][x] = 0.f;

#pragma unroll 2
    for (int ks = 0; ks < 8; ks++) {
        uint32_t Ah[2][4], Al[2][4];
#pragma unroll
        for (int mt = 0; mt < 2; mt++) {
            int r = wm * 32 + mt * 16 + g;
            int kp = ks * 8 + q;
            Ah[mt][0] = a2hi[r * 68 + kp];
            Ah[mt][1] = a2hi[(r + 8) * 68 + kp];
            Ah[mt][2] = a2hi[r * 68 + kp + 4];
            Ah[mt][3] = a2hi[(r + 8) * 68 + kp + 4];
            Al[mt][0] = a2lo[r * 68 + kp];
            Al[mt][1] = a2lo[(r + 8) * 68 + kp];
            Al[mt][2] = a2lo[r * 68 + kp + 4];
            Al[mt][3] = a2lo[(r + 8) * 68 + kp + 4];
        }
#pragma unroll
        for (int nt = 0; nt < 8; nt++) {
            int n = wn * 64 + nt * 8 + g;
            uint32_t bh[2], bl[2];
            bh[0] = __ldg(&g_w2f_hi[n * 64 + ks * 8 + q]);
            bh[1] = __ldg(&g_w2f_hi[n * 64 + ks * 8 + 4 + q]);
            bl[0] = __ldg(&g_w2f_lo[n * 64 + ks * 8 + q]);
            bl[1] = __ldg(&g_w2f_lo[n * 64 + ks * 8 + 4 + q]);
#pragma unroll
            for (int mt = 0; mt < 2; mt++) {
                mma_bf16(acc[mt][nt], Ah[mt], bh);
                mma_bf16(acc[mt][nt], Al[mt], bh);
                mma_bf16(acc[mt][nt], Ah[mt], bl);
            }
        }
    }
    __syncthreads();   // all warps done reading A2 before h1f overlay

    // ===== epilogue 2: bias + relu -> m; gate partials; m -> h1f =====
    {
        float gp0 = 0.f, gp1 = 0.f, gp2 = 0.f, gp3 = 0.f;
#pragma unroll
        for (int mt = 0; mt < 2; mt++)
#pragma unroll
        for (int nt = 0; nt < 8; nt++) {
            int r = wm * 32 + mt * 16 + g;
            int c = wn * 64 + nt * 8 + q * 2;
            float2 b2v = __ldg((const float2*)&b2[c]);
            float2 wgv = __ldg((const float2*)&Wg[c]);
            float m0 = fmaxf(acc[mt][nt][0] + b2v.x, 0.f);
            float m1 = fmaxf(acc[mt][nt][1] + b2v.y, 0.f);
            float m2 = fmaxf(acc[mt][nt][2] + b2v.x, 0.f);
            float m3 = fmaxf(acc[mt][nt][3] + b2v.y, 0.f);
            float d0 = m0 * wgv.x + m1 * wgv.y;
            float d1 = m2 * wgv.x + m3 * wgv.y;
            if (mt == 0) { gp0 += d0; gp1 += d1; } else { gp2 += d0; gp3 += d1; }
            *(float2*)&h1f[r * 132 + c]       = make_float2(m0, m1);
            *(float2*)&h1f[(r + 8) * 132 + c] = make_float2(m2, m3);
        }
        atomicAdd(&gsm[wm * 32 + g],      gp0);
        atomicAdd(&gsm[wm * 32 + g + 8],  gp1);
        atomicAdd(&gsm[wm * 32 + g + 16], gp2);
        atomicAdd(&gsm[wm * 32 + g + 24], gp3);
    }
    __syncthreads();
    if (tid < 128) gsm[tid] = 1.f / (1.f + expf(-(gsm[tid] + __ldg(bg))));
    __syncthreads();

    // ===== scatter: mi[dst] += m * g =====
    {
        float* g_mif = (float*)g_mi4;
        for (int i = tid; i < 128 * 32; i += 256) {
            int row = i >> 5, j = i & 31;
            float4 v = *(float4*)&h1f[row * 132 + j * 4];
            float gg = gsm[row];
            atomicAdd((float4*)&g_mif[dsts[row] * 128 + j * 4],
                      make_float4(v.x * gg, v.y * gg, v.z * gg, v.w * gg));
        }
    }
}

// ---------------- node kernel (scalar f32x2, known correct) ----------------
#define TE 64
#define HS 132
#define YS 260

extern "C" __global__ void __launch_bounds__(256)
node_kernel(const float* __restrict__ h,
            const float* __restrict__ Wn1, const float* __restrict__ bn1,
            const float* __restrict__ Wn2, const float* __restrict__ bn2,
            float* __restrict__ out)
{
    extern __shared__ float smem[];
    float* ys  = smem;
    float* h1s = ys + TE * YS;
    float* ws  = h1s + TE * HS;

    const int tid = threadIdx.x;
    const int n0  = blockIdx.x * TE;

    {
        const float4* h4 = (const float4*)h;
        const float4* m4 = (const float4*)g_mi4;
        for (int i = tid; i < TE * 64; i += 256) {
            int n = i >> 6, j = i & 63;
            int gn = n0 + n;
            float4 v = make_float4(0.f, 0.f, 0.f, 0.f);
            int off;
            if (j < 32) { if (gn < N_NODES) v = m4[gn * 32 + j]; off = j * 4; }
            else        { if (gn < N_NODES) v = h4[gn * 32 + (j - 32)]; off = 128 + (j - 32) * 4; }
            *(float4*)&ys[n * YS + off] = v;
        }
    }

    const int ty = tid >> 4, tx = tid & 15;
    const int er = ty * 4, cc = tx * 8;

    ull acc[4][4];
#pragma unroll
    for (int e = 0; e < 4; e++)
#pragma unroll
        for (int c = 0; c < 4; c++) acc[e][c] = 0ULL;

    for (int kt = 0; kt < 2 * HID; kt += 16) {
        __syncthreads();
        {
            int r = tid >> 4, c8 = (tid & 15) * 8;
            *(float4*)&ws[r * 128 + c8]     = *(const float4*)&Wn1[(kt + r) * 128 + c8];
            *(float4*)&ws[r * 128 + c8 + 4] = *(const float4*)&Wn1[(kt + r) * 128 + c8 + 4];
        }
        __syncthreads();
#pragma unroll
        for (int k = 0; k < 16; ++k) {
            const ull* wp = (const ull*)&ws[k * 128 + cc];
            ull w0 = wp[0], w1 = wp[1], w2 = wp[2], w3 = wp[3];
#pragma unroll
            for (int e = 0; e < 4; ++e) {
                float xv = ys[(er + e) * YS + kt + k];
                ull xd = pack2(xv, xv);
                acc[e][0] = fma2(xd, w0, acc[e][0]);
                acc[e][1] = fma2(xd, w1, acc[e][1]);
                acc[e][2] = fma2(xd, w2, acc[e][2]);
                acc[e][3] = fma2(xd, w3, acc[e][3]);
            }
        }
    }
    {
        float4 bA = *(const float4*)&bn1[cc];
        float4 bB = *(const float4*)&bn1[cc + 4];
#pragma unroll
        for (int e = 0; e < 4; e++) {
            float2 p0 = unpack2(acc[e][0]), p1 = unpack2(acc[e][1]);
            float2 p2 = unpack2(acc[e][2]), p3 = unpack2(acc[e][3]);
            float4 o0 = make_float4(fmaxf(p0.x + bA.x, 0.f), fmaxf(p0.y + bA.y, 0.f),
                                    fmaxf(p1.x + bA.z, 0.f), fmaxf(p1.y + bA.w, 0.f));
            float4 o1 = make_float4(fmaxf(p2.x + bB.x, 0.f), fmaxf(p2.y + bB.y, 0.f),
                                    fmaxf(p3.x + bB.z, 0.f), fmaxf(p3.y + bB.w, 0.f));
            *(float4*)&h1s[(er + e) * HS + cc]     = o0;
            *(float4*)&h1s[(er + e) * HS + cc + 4] = o1;
        }
    }

    ull acc2[4][4];
#pragma unroll
    for (int e = 0; e < 4; e++)
#pragma unroll
        for (int c = 0; c < 4; c++) acc2[e][c] = 0ULL;

    for (int kt = 0; kt < HID; kt += 16) {
        __syncthreads();
        {
            int r = tid >> 4, c8 = (tid & 15) * 8;
            *(float4*)&ws[r * 128 + c8]     = *(const float4*)&Wn2[(kt + r) * 128 + c8];
            *(float4*)&ws[r * 128 + c8 + 4] = *(const float4*)&Wn2[(kt + r) * 128 + c8 + 4];
        }
        __syncthreads();
#pragma unroll
        for (int k = 0; k < 16; ++k) {
            const ull* wp = (const ull*)&ws[k * 128 + cc];
            ull w0 = wp[0], w1 = wp[1], w2 = wp[2], w3 = wp[3];
#pragma unroll
            for (int e = 0; e < 4; ++e) {
                float xv = h1s[(er + e) * HS + kt + k];
                ull xd = pack2(xv, xv);
                acc2[e][0] = fma2(xd, w0, acc2[e][0]);
                acc2[e][1] = fma2(xd, w1, acc2[e][1]);
                acc2[e][2] = fma2(xd, w2, acc2[e][2]);
                acc2[e][3] = fma2(xd, w3, acc2[e][3]);
            }
        }
    }
    {
        float4 bA = *(const float4*)&bn2[cc];
        float4 bB = *(const float4*)&bn2[cc + 4];
#pragma unroll
        for (int e = 0; e < 4; e++) {
            int gn = n0 + er + e;
            if (gn >= N_NODES) continue;
            float2 p0 = unpack2(acc2[e][0]), p1 = unpack2(acc2[e][1]);
            float2 p2 = unpack2(acc2[e][2]), p3 = unpack2(acc2[e][3]);
            float4 o0 = make_float4(p0.x + bA.x, p0.y + bA.y, p1.x + bA.z, p1.y + bA.w);
            float4 o1 = make_float4(p2.x + bB.x, p2.y + bB.y, p3.x + bB.z, p3.y + bB.w);
            *(float4*)&out[gn * HID + cc]     = o0;
            *(float4*)&out[gn * HID + cc + 4] = o1;
        }
    }
}

// ---------------- launch ----------------
extern "C" void kernel_launch(void* const* d_in, const int* in_sizes, int n_in,
                              void* d_out, int out_size)
{
    const float* h   = (const float*)d_in[0];
    const int*   ei  = (const int*)d_in[1];
    const float* ea  = (const float*)d_in[2];
    const float* We1 = (const float*)d_in[3];
    const float* b1  = (const float*)d_in[4];
    const float* We2 = (const float*)d_in[5];
    const float* b2  = (const float*)d_in[6];
    const float* Wg  = (const float*)d_in[7];
    const float* bg  = (const float*)d_in[8];
    const float* Wn1 = (const float*)d_in[9];
    const float* bn1 = (const float*)d_in[10];
    const float* Wn2 = (const float*)d_in[11];
    const float* bn2 = (const float*)d_in[12];
    float* out = (float*)d_out;

    size_t smem_n = (size_t)(TE * YS + TE * HS + 16 * 128) * sizeof(float);
    cudaFuncSetAttribute(edge_kernel, cudaFuncAttributeMaxDynamicSharedMemorySize, SMEM_EDGE);
    cudaFuncSetAttribute(node_kernel, cudaFuncAttributeMaxDynamicSharedMemorySize, (int)smem_n);

    zero_mi_kernel<<<(N_NODES * (HID / 4)) / 512, 512>>>();
    prep_frag_kernel<<<(2048 + 8192 + 255) / 256, 256>>>(We1, We2);
    pq_kernel<<<dim3((N_NODES + 63) / 64, 2), 256>>>(h, We1);
    edge_kernel<<<N_EDGES / 128, 256, SMEM_EDGE>>>(ei, ea, b1, b2, Wg, bg);
    node_kernel<<<(N_NODES + TE - 1) / TE, 256, smem_n>>>(h, Wn1, bn1, Wn2, bn2, out);
}

// round 4
// speedup vs baseline: 3.9335x; 1.4247x over previous
#include <cuda_runtime.h>
#include <cuda_bf16.h>
#include <cstdint>

#define N_NODES 50000
#define N_EDGES 800000
#define HID 128

typedef unsigned long long ull;

// ---------------- device-global scratch (no allocations allowed) ----------------
__device__ float4 g_mi4[N_NODES * (HID / 4)];
__device__ float g_P[N_NODES * HID];          // h @ We1[24:152]
__device__ float g_Q[N_NODES * HID];          // h @ We1[152:280]
// B fragments packed as uint4 {bh0, bh1, bl0, bl1}
__device__ uint4 g_w1f4[128 * 8];             // We1[0:24] (K padded to 32): [n][ks*4+q]
__device__ uint4 g_w2f4[128 * 32];            // We2: [n][ks*4+q]

// ---------------- helpers ----------------
__device__ __forceinline__ void split_pack(float v0, float v1, uint32_t& hi, uint32_t& lo) {
    __nv_bfloat162 h2 = __floats2bfloat162_rn(v0, v1);
    float r0 = v0 - __bfloat162float(h2.x);
    float r1 = v1 - __bfloat162float(h2.y);
    __nv_bfloat162 l2 = __floats2bfloat162_rn(r0, r1);
    hi = *reinterpret_cast<uint32_t*>(&h2);
    lo = *reinterpret_cast<uint32_t*>(&l2);
}

__device__ __forceinline__ void mma_bf16(float* d, const uint32_t* a, const uint32_t* b) {
    asm volatile("mma.sync.aligned.m16n8k16.row.col.f32.bf16.bf16.f32 "
        "{%0,%1,%2,%3}, {%4,%5,%6,%7}, {%8,%9}, {%0,%1,%2,%3};"
        : "+f"(d[0]), "+f"(d[1]), "+f"(d[2]), "+f"(d[3])
        : "r"(a[0]), "r"(a[1]), "r"(a[2]), "r"(a[3]), "r"(b[0]), "r"(b[1]));
}

__device__ __forceinline__ ull pack2(float lo, float hi) {
    ull r; asm("mov.b64 %0, {%1, %2};" : "=l"(r) : "f"(lo), "f"(hi)); return r;
}
__device__ __forceinline__ float2 unpack2(ull v) {
    float2 r; asm("mov.b64 {%0, %1}, %2;" : "=f"(r.x), "=f"(r.y) : "l"(v)); return r;
}
__device__ __forceinline__ ull fma2(ull a, ull b, ull c) {
    ull d; asm("fma.rn.f32x2 %0, %1, %2, %3;" : "=l"(d) : "l"(a), "l"(b), "l"(c)); return d;
}

// ---------------- small kernels ----------------
__global__ void zero_mi_kernel() {
    int i = blockIdx.x * blockDim.x + threadIdx.x;
    g_mi4[i] = make_float4(0.f, 0.f, 0.f, 0.f);
}

// pack B fragments: for (n, ks, q): {hi(kp0), hi(kp1), lo(kp0), lo(kp1)},
// kp0 = ks*8+q, kp1 = ks*8+4+q, value(kp) = bf16 pair of W[2kp][n], W[2kp+1][n]
__global__ void prep_frag_kernel(const float* __restrict__ W1, const float* __restrict__ W2) {
    int i = blockIdx.x * blockDim.x + threadIdx.x;
    if (i < 1024) {
        int n = i >> 3, t = i & 7, ks = t >> 2, q = t & 3;
        int kp0 = ks * 8 + q, kp1 = ks * 8 + 4 + q;
        float a0 = (2 * kp0     < 24) ? W1[(2 * kp0)     * 128 + n] : 0.f;
        float a1 = (2 * kp0 + 1 < 24) ? W1[(2 * kp0 + 1) * 128 + n] : 0.f;
        float b0 = (2 * kp1     < 24) ? W1[(2 * kp1)     * 128 + n] : 0.f;
        float b1 = (2 * kp1 + 1 < 24) ? W1[(2 * kp1 + 1) * 128 + n] : 0.f;
        uint32_t h0, l0, h1, l1;
        split_pack(a0, a1, h0, l0);
        split_pack(b0, b1, h1, l1);
        g_w1f4[i] = make_uint4(h0, h1, l0, l1);
    } else if (i < 1024 + 4096) {
        int t2 = i - 1024;
        int n = t2 >> 5, t = t2 & 31, ks = t >> 2, q = t & 3;
        int kp0 = ks * 8 + q, kp1 = ks * 8 + 4 + q;
        float a0 = W2[(2 * kp0)     * 128 + n];
        float a1 = W2[(2 * kp0 + 1) * 128 + n];
        float b0 = W2[(2 * kp1)     * 128 + n];
        float b1 = W2[(2 * kp1 + 1) * 128 + n];
        uint32_t h0, l0, h1, l1;
        split_pack(a0, a1, h0, l0);
        split_pack(b0, b1, h1, l1);
        g_w2f4[t2] = make_uint4(h0, h1, l0, l1);
    }
}

// ---------------- P/Q precompute: P = h @ We1[24:152], Q = h @ We1[152:280] ----------------
extern "C" __global__ void __launch_bounds__(256)
pq_kernel(const float* __restrict__ h, const float* __restrict__ We1) {
    __shared__ float ys[64 * 132];
    __shared__ float ws[16 * 128];
    const int tid = threadIdx.x;
    const int n0 = blockIdx.x * 64;
    const float* W = We1 + (24 + blockIdx.y * 128) * 128;
    float* Pout = (blockIdx.y == 0) ? g_P : g_Q;

    {
        const float4* h4 = (const float4*)h;
        for (int i = tid; i < 64 * 32; i += 256) {
            int n = i >> 5, j = i & 31;
            int gn = n0 + n;
            float4 v = make_float4(0.f, 0.f, 0.f, 0.f);
            if (gn < N_NODES) v = h4[gn * 32 + j];
            *(float4*)&ys[n * 132 + j * 4] = v;
        }
    }

    const int ty = tid >> 4, tx = tid & 15;
    const int er = ty * 4, cc = tx * 8;

    ull acc[4][4];
#pragma unroll
    for (int e = 0; e < 4; e++)
#pragma unroll
        for (int c = 0; c < 4; c++) acc[e][c] = 0ULL;

    for (int kt = 0; kt < 128; kt += 16) {
        __syncthreads();
        {
            int r = tid >> 4, c8 = (tid & 15) * 8;
            *(float4*)&ws[r * 128 + c8]     = *(const float4*)&W[(kt + r) * 128 + c8];
            *(float4*)&ws[r * 128 + c8 + 4] = *(const float4*)&W[(kt + r) * 128 + c8 + 4];
        }
        __syncthreads();
#pragma unroll
        for (int k = 0; k < 16; ++k) {
            const ull* wp = (const ull*)&ws[k * 128 + cc];
            ull w0 = wp[0], w1 = wp[1], w2 = wp[2], w3 = wp[3];
#pragma unroll
            for (int e = 0; e < 4; ++e) {
                float xv = ys[(er + e) * 132 + kt + k];
                ull xd = pack2(xv, xv);
                acc[e][0] = fma2(xd, w0, acc[e][0]);
                acc[e][1] = fma2(xd, w1, acc[e][1]);
                acc[e][2] = fma2(xd, w2, acc[e][2]);
                acc[e][3] = fma2(xd, w3, acc[e][3]);
            }
        }
    }
#pragma unroll
    for (int e = 0; e < 4; e++) {
        int gn = n0 + er + e;
        if (gn >= N_NODES) continue;
        float2 p0 = unpack2(acc[e][0]), p1 = unpack2(acc[e][1]);
        float2 p2 = unpack2(acc[e][2]), p3 = unpack2(acc[e][3]);
        *(float4*)&Pout[gn * 128 + cc]     = make_float4(p0.x, p0.y, p1.x, p1.y);
        *(float4*)&Pout[gn * 128 + cc + 4] = make_float4(p2.x, p2.y, p3.x, p3.y);
    }
}

// ---------------- edge kernel ----------------
// smem (bytes): a2hi uint4[2048] @0 (32KB, overlays eas[128*24] used only in phase 1);
//               a2lo uint4[2048] @32768 (32KB);
//               dsts @65536 (512); srcs @66048 (512); gsm @66560 (512)
#define SMEM_EDGE 67072

extern "C" __global__ void __launch_bounds__(256, 2)
edge_kernel(const int* __restrict__ ei, const float* __restrict__ ea,
            const float* __restrict__ b1, const float* __restrict__ b2,
            const float* __restrict__ Wg, const float* __restrict__ bg)
{
    extern __shared__ __align__(16) char sm[];
    uint4* a2hi4 = (uint4*)sm;
    uint4* a2lo4 = (uint4*)(sm + 32768);
    float* eas   = (float*)sm;            // overlay, phase-1 only
    int*   dsts  = (int*)(sm + 65536);
    int*   srcs  = (int*)(sm + 66048);
    float* gsm   = (float*)(sm + 66560);

    const int tid = threadIdx.x;
    const int wid = tid >> 5, lane = tid & 31;
    const int g = lane >> 2, q = lane & 3;
    const int wm = wid & 3, wn = wid >> 2;
    const int e0 = blockIdx.x * 128;

    if (tid < 128) {
        dsts[tid] = ei[e0 + tid];
        srcs[tid] = ei[N_EDGES + e0 + tid];
        gsm[tid] = 0.f;
    }
    {
        const float4* ea4 = (const float4*)ea;
        for (int i = tid; i < 128 * 6; i += 256) {
            int e = i / 6, j = i % 6;
            *(float4*)&eas[e * 24 + j * 4] = ea4[(e0 + e) * 6 + j];
        }
    }
    __syncthreads();

    float acc[2][8][4];
#pragma unroll
    for (int mt = 0; mt < 2; mt++)
#pragma unroll
        for (int nt = 0; nt < 8; nt++)
#pragma unroll
            for (int x = 0; x < 4; x++) acc[mt][nt][x] = 0.f;

    // ===== phase 1: ea @ W1a (K=24 padded to 32), bf16 3-term split =====
#pragma unroll
    for (int ks = 0; ks < 2; ks++) {
        uint32_t Ah[2][4], Al[2][4];
#pragma unroll
        for (int mt = 0; mt < 2; mt++) {
            int r = wm * 32 + mt * 16 + g;
            int k0 = ks * 16 + q * 2;
            int k8 = k0 + 8;
            float v00 = eas[r * 24 + k0];
            float v01 = eas[r * 24 + k0 + 1];
            split_pack(v00, v01, Ah[mt][0], Al[mt][0]);
            float v10 = eas[(r + 8) * 24 + k0];
            float v11 = eas[(r + 8) * 24 + k0 + 1];
            split_pack(v10, v11, Ah[mt][1], Al[mt][1]);
            float v20 = (k8 < 24) ? eas[r * 24 + k8] : 0.f;
            float v21 = (k8 < 24) ? eas[r * 24 + k8 + 1] : 0.f;
            split_pack(v20, v21, Ah[mt][2], Al[mt][2]);
            float v30 = (k8 < 24) ? eas[(r + 8) * 24 + k8] : 0.f;
            float v31 = (k8 < 24) ? eas[(r + 8) * 24 + k8 + 1] : 0.f;
            split_pack(v30, v31, Ah[mt][3], Al[mt][3]);
        }
#pragma unroll
        for (int nt = 0; nt < 8; nt++) {
            int n = wn * 64 + nt * 8 + g;
            uint4 w = __ldg(&g_w1f4[n * 8 + ks * 4 + q]);
            uint32_t bh[2] = {w.x, w.y};
            uint32_t bl[2] = {w.z, w.w};
#pragma unroll
            for (int mt = 0; mt < 2; mt++) {
                mma_bf16(acc[mt][nt], Ah[mt], bh);
                mma_bf16(acc[mt][nt], Al[mt], bh);
                mma_bf16(acc[mt][nt], Ah[mt], bl);
            }
        }
    }
    __syncthreads();   // all warps done reading eas before a2 overlay writes

    // ===== epilogue 1: + P[dst] + Q[src] + b1, relu, split -> a2 fragment layout =====
#pragma unroll
    for (int mt = 0; mt < 2; mt++) {
        int r = wm * 32 + mt * 16 + g;
        int d0 = dsts[r], s0 = srcs[r];
        int d8 = dsts[r + 8], s8 = srcs[r + 8];
#pragma unroll
        for (int j = 0; j < 4; j++) {
            uint32_t hi[4], lo[4];
#pragma unroll
            for (int u = 0; u < 2; u++) {
                int nt = 2 * j + u;
                int c = wn * 64 + nt * 8 + q * 2;
                float2 b1v = __ldg((const float2*)&b1[c]);
                float2 pv0 = __ldg((const float2*)&g_P[d0 * 128 + c]);
                float2 qv0 = __ldg((const float2*)&g_Q[s0 * 128 + c]);
                float t0 = fmaxf(acc[mt][nt][0] + pv0.x + qv0.x + b1v.x, 0.f);
                float t1 = fmaxf(acc[mt][nt][1] + pv0.y + qv0.y + b1v.y, 0.f);
                split_pack(t0, t1, hi[2 * u], lo[2 * u]);
                float2 pv8 = __ldg((const float2*)&g_P[d8 * 128 + c]);
                float2 qv8 = __ldg((const float2*)&g_Q[s8 * 128 + c]);
                float t2 = fmaxf(acc[mt][nt][2] + pv8.x + qv8.x + b1v.x, 0.f);
                float t3 = fmaxf(acc[mt][nt][3] + pv8.y + qv8.y + b1v.y, 0.f);
                split_pack(t2, t3, hi[2 * u + 1], lo[2 * u + 1]);
            }
            int K8 = wn * 4 + j;
            int idx = (((wm * 2 + mt) * 8 + K8) * 8 + g) * 4 + q;
            a2hi4[idx] = make_uint4(hi[0], hi[1], hi[2], hi[3]);
            a2lo4[idx] = make_uint4(lo[0], lo[1], lo[2], lo[3]);
        }
    }
    __syncthreads();

    // ===== phase 2: layer2 [128x128] @ [128x128], bf16 3-term split =====
#pragma unroll
    for (int mt = 0; mt < 2; mt++)
#pragma unroll
        for (int nt = 0; nt < 8; nt++)
#pragma unroll
            for (int x = 0; x < 4; x++) acc[mt][nt][x] = 0.f;

#pragma unroll 2
    for (int ks = 0; ks < 8; ks++) {
        uint32_t Ah[2][4], Al[2][4];
#pragma unroll
        for (int mt = 0; mt < 2; mt++) {
            int idx = (((wm * 2 + mt) * 8 + ks) * 8 + g) * 4 + q;
            uint4 vh = a2hi4[idx];
            Ah[mt][0] = vh.x; Ah[mt][1] = vh.y; Ah[mt][2] = vh.z; Ah[mt][3] = vh.w;
            uint4 vl = a2lo4[idx];
            Al[mt][0] = vl.x; Al[mt][1] = vl.y; Al[mt][2] = vl.z; Al[mt][3] = vl.w;
        }
#pragma unroll
        for (int nt = 0; nt < 8; nt++) {
            int n = wn * 64 + nt * 8 + g;
            uint4 w = __ldg(&g_w2f4[n * 32 + ks * 4 + q]);
            uint32_t bh[2] = {w.x, w.y};
            uint32_t bl[2] = {w.z, w.w};
#pragma unroll
            for (int mt = 0; mt < 2; mt++) {
                mma_bf16(acc[mt][nt], Ah[mt], bh);
                mma_bf16(acc[mt][nt], Al[mt], bh);
                mma_bf16(acc[mt][nt], Ah[mt], bl);
            }
        }
    }

    // ===== epilogue 2: bias + relu -> m (kept in regs); gate partials =====
    {
        float gp[2][2] = {{0.f, 0.f}, {0.f, 0.f}};
#pragma unroll
        for (int mt = 0; mt < 2; mt++)
#pragma unroll
        for (int nt = 0; nt < 8; nt++) {
            int c = wn * 64 + nt * 8 + q * 2;
            float2 b2v = __ldg((const float2*)&b2[c]);
            float2 wgv = __ldg((const float2*)&Wg[c]);
            float m0 = fmaxf(acc[mt][nt][0] + b2v.x, 0.f);
            float m1 = fmaxf(acc[mt][nt][1] + b2v.y, 0.f);
            float m2 = fmaxf(acc[mt][nt][2] + b2v.x, 0.f);
            float m3 = fmaxf(acc[mt][nt][3] + b2v.y, 0.f);
            gp[mt][0] += m0 * wgv.x + m1 * wgv.y;
            gp[mt][1] += m2 * wgv.x + m3 * wgv.y;
            acc[mt][nt][0] = m0; acc[mt][nt][1] = m1;
            acc[mt][nt][2] = m2; acc[mt][nt][3] = m3;
        }
#pragma unroll
        for (int mt = 0; mt < 2; mt++) {
            atomicAdd(&gsm[wm * 32 + mt * 16 + g],     gp[mt][0]);
            atomicAdd(&gsm[wm * 32 + mt * 16 + g + 8], gp[mt][1]);
        }
    }
    __syncthreads();
    if (tid < 128) gsm[tid] = 1.f / (1.f + expf(-(gsm[tid] + __ldg(bg))));
    __syncthreads();

    // ===== scatter from registers: mi[dst] += m * g (float2 global REDs) =====
    {
        float* g_mif = (float*)g_mi4;
#pragma unroll
        for (int mt = 0; mt < 2; mt++) {
            int r = wm * 32 + mt * 16 + g;
            float gg0 = gsm[r], gg1 = gsm[r + 8];
            int d0 = dsts[r], d8 = dsts[r + 8];
#pragma unroll
            for (int nt = 0; nt < 8; nt++) {
                int c = wn * 64 + nt * 8 + q * 2;
                atomicAdd((float2*)&g_mif[d0 * 128 + c],
                          make_float2(acc[mt][nt][0] * gg0, acc[mt][nt][1] * gg0));
                atomicAdd((float2*)&g_mif[d8 * 128 + c],
                          make_float2(acc[mt][nt][2] * gg1, acc[mt][nt][3] * gg1));
            }
        }
    }
}

// ---------------- node kernel (scalar f32x2, known correct) ----------------
#define TE 64
#define HS 132
#define YS 260

extern "C" __global__ void __launch_bounds__(256)
node_kernel(const float* __restrict__ h,
            const float* __restrict__ Wn1, const float* __restrict__ bn1,
            const float* __restrict__ Wn2, const float* __restrict__ bn2,
            float* __restrict__ out)
{
    extern __shared__ float smem[];
    float* ys  = smem;
    float* h1s = ys + TE * YS;
    float* ws  = h1s + TE * HS;

    const int tid = threadIdx.x;
    const int n0  = blockIdx.x * TE;

    {
        const float4* h4 = (const float4*)h;
        const float4* m4 = (const float4*)g_mi4;
        for (int i = tid; i < TE * 64; i += 256) {
            int n = i >> 6, j = i & 63;
            int gn = n0 + n;
            float4 v = make_float4(0.f, 0.f, 0.f, 0.f);
            int off;
            if (j < 32) { if (gn < N_NODES) v = m4[gn * 32 + j]; off = j * 4; }
            else        { if (gn < N_NODES) v = h4[gn * 32 + (j - 32)]; off = 128 + (j - 32) * 4; }
            *(float4*)&ys[n * YS + off] = v;
        }
    }

    const int ty = tid >> 4, tx = tid & 15;
    const int er = ty * 4, cc = tx * 8;

    ull acc[4][4];
#pragma unroll
    for (int e = 0; e < 4; e++)
#pragma unroll
        for (int c = 0; c < 4; c++) acc[e][c] = 0ULL;

    for (int kt = 0; kt < 2 * HID; kt += 16) {
        __syncthreads();
        {
            int r = tid >> 4, c8 = (tid & 15) * 8;
            *(float4*)&ws[r * 128 + c8]     = *(const float4*)&Wn1[(kt + r) * 128 + c8];
            *(float4*)&ws[r * 128 + c8 + 4] = *(const float4*)&Wn1[(kt + r) * 128 + c8 + 4];
        }
        __syncthreads();
#pragma unroll
        for (int k = 0; k < 16; ++k) {
            const ull* wp = (const ull*)&ws[k * 128 + cc];
            ull w0 = wp[0], w1 = wp[1], w2 = wp[2], w3 = wp[3];
#pragma unroll
            for (int e = 0; e < 4; ++e) {
                float xv = ys[(er + e) * YS + kt + k];
                ull xd = pack2(xv, xv);
                acc[e][0] = fma2(xd, w0, acc[e][0]);
                acc[e][1] = fma2(xd, w1, acc[e][1]);
                acc[e][2] = fma2(xd, w2, acc[e][2]);
                acc[e][3] = fma2(xd, w3, acc[e][3]);
            }
        }
    }
    {
        float4 bA = *(const float4*)&bn1[cc];
        float4 bB = *(const float4*)&bn1[cc + 4];
#pragma unroll
        for (int e = 0; e < 4; e++) {
            float2 p0 = unpack2(acc[e][0]), p1 = unpack2(acc[e][1]);
            float2 p2 = unpack2(acc[e][2]), p3 = unpack2(acc[e][3]);
            float4 o0 = make_float4(fmaxf(p0.x + bA.x, 0.f), fmaxf(p0.y + bA.y, 0.f),
                                    fmaxf(p1.x + bA.z, 0.f), fmaxf(p1.y + bA.w, 0.f));
            float4 o1 = make_float4(fmaxf(p2.x + bB.x, 0.f), fmaxf(p2.y + bB.y, 0.f),
                                    fmaxf(p3.x + bB.z, 0.f), fmaxf(p3.y + bB.w, 0.f));
            *(float4*)&h1s[(er + e) * HS + cc]     = o0;
            *(float4*)&h1s[(er + e) * HS + cc + 4] = o1;
        }
    }

    ull acc2[4][4];
#pragma unroll
    for (int e = 0; e < 4; e++)
#pragma unroll
        for (int c = 0; c < 4; c++) acc2[e][c] = 0ULL;

    for (int kt = 0; kt < HID; kt += 16) {
        __syncthreads();
        {
            int r = tid >> 4, c8 = (tid & 15) * 8;
            *(float4*)&ws[r * 128 + c8]     = *(const float4*)&Wn2[(kt + r) * 128 + c8];
            *(float4*)&ws[r * 128 + c8 + 4] = *(const float4*)&Wn2[(kt + r) * 128 + c8 + 4];
        }
        __syncthreads();
#pragma unroll
        for (int k = 0; k < 16; ++k) {
            const ull* wp = (const ull*)&ws[k * 128 + cc];
            ull w0 = wp[0], w1 = wp[1], w2 = wp[2], w3 = wp[3];
#pragma unroll
            for (int e = 0; e < 4; ++e) {
                float xv = h1s[(er + e) * HS + kt + k];
                ull xd = pack2(xv, xv);
                acc2[e][0] = fma2(xd, w0, acc2[e][0]);
                acc2[e][1] = fma2(xd, w1, acc2[e][1]);
                acc2[e][2] = fma2(xd, w2, acc2[e][2]);
                acc2[e][3] = fma2(xd, w3, acc2[e][3]);
            }
        }
    }
    {
        float4 bA = *(const float4*)&bn2[cc];
        float4 bB = *(const float4*)&bn2[cc + 4];
#pragma unroll
        for (int e = 0; e < 4; e++) {
            int gn = n0 + er + e;
            if (gn >= N_NODES) continue;
            float2 p0 = unpack2(acc2[e][0]), p1 = unpack2(acc2[e][1]);
            float2 p2 = unpack2(acc2[e][2]), p3 = unpack2(acc2[e][3]);
            float4 o0 = make_float4(p0.x + bA.x, p0.y + bA.y, p1.x + bA.z, p1.y + bA.w);
            float4 o1 = make_float4(p2.x + bB.x, p2.y + bB.y, p3.x + bB.z, p3.y + bB.w);
            *(float4*)&out[gn * HID + cc]     = o0;
            *(float4*)&out[gn * HID + cc + 4] = o1;
        }
    }
}

// ---------------- launch ----------------
extern "C" void kernel_launch(void* const* d_in, const int* in_sizes, int n_in,
                              void* d_out, int out_size)
{
    const float* h   = (const float*)d_in[0];
    const int*   ei  = (const int*)d_in[1];
    const float* ea  = (const float*)d_in[2];
    const float* We1 = (const float*)d_in[3];
    const float* b1  = (const float*)d_in[4];
    const float* We2 = (const float*)d_in[5];
    const float* b2  = (const float*)d_in[6];
    const float* Wg  = (const float*)d_in[7];
    const float* bg  = (const float*)d_in[8];
    const float* Wn1 = (const float*)d_in[9];
    const float* bn1 = (const float*)d_in[10];
    const float* Wn2 = (const float*)d_in[11];
    const float* bn2 = (const float*)d_in[12];
    float* out = (float*)d_out;

    size_t smem_n = (size_t)(TE * YS + TE * HS + 16 * 128) * sizeof(float);
    cudaFuncSetAttribute(edge_kernel, cudaFuncAttributeMaxDynamicSharedMemorySize, SMEM_EDGE);
    cudaFuncSetAttribute(node_kernel, cudaFuncAttributeMaxDynamicSharedMemorySize, (int)smem_n);

    zero_mi_kernel<<<(N_NODES * (HID / 4)) / 512, 512>>>();
    prep_frag_kernel<<<(1024 + 4096 + 255) / 256, 256>>>(We1, We2);
    pq_kernel<<<dim3((N_NODES + 63) / 64, 2), 256>>>(h, We1);
    edge_kernel<<<N_EDGES / 128, 256, SMEM_EDGE>>>(ei, ea, b1, b2, Wg, bg);
    node_kernel<<<(N_NODES + TE - 1) / TE, 256, smem_n>>>(h, Wn1, bn1, Wn2, bn2, out);
}

// round 5
// speedup vs baseline: 5.7934x; 1.4728x over previous
#include <cuda_runtime.h>
#include <cuda_bf16.h>
#include <cstdint>

#define N_NODES 50000
#define N_EDGES 800000
#define HID 128

typedef unsigned long long ull;

// ---------------- device-global scratch (no allocations allowed) ----------------
__device__ float4 g_mi4[N_NODES * (HID / 4)];
__device__ float g_P[N_NODES * HID];          // h @ We1[24:152]
__device__ float g_Q[N_NODES * HID];          // h @ We1[152:280]
// B fragments packed as uint4 {bh0, bh1, bl0, bl1}
__device__ uint4 g_w1f4[128 * 8];             // We1[0:24] (K padded to 32): [n][ks*4+q]
__device__ uint4 g_w2f4[128 * 32];            // We2: [n][ks*4+q]
__device__ uint4 g_wpf4[128 * 32];            // We1[24:152]  (P weights)
__device__ uint4 g_wqf4[128 * 32];            // We1[152:280] (Q weights)
__device__ uint4 g_wn1f4[128 * 64];           // Wn1 (K=256): [n][ks*4+q], ks 0..15
__device__ uint4 g_wn2f4[128 * 32];           // Wn2

// ---------------- helpers ----------------
__device__ __forceinline__ void split_pack(float v0, float v1, uint32_t& hi, uint32_t& lo) {
    __nv_bfloat162 h2 = __floats2bfloat162_rn(v0, v1);
    float r0 = v0 - __bfloat162float(h2.x);
    float r1 = v1 - __bfloat162float(h2.y);
    __nv_bfloat162 l2 = __floats2bfloat162_rn(r0, r1);
    hi = *reinterpret_cast<uint32_t*>(&h2);
    lo = *reinterpret_cast<uint32_t*>(&l2);
}

__device__ __forceinline__ void mma_bf16(float* d, const uint32_t* a, const uint32_t* b) {
    asm volatile("mma.sync.aligned.m16n8k16.row.col.f32.bf16.bf16.f32 "
        "{%0,%1,%2,%3}, {%4,%5,%6,%7}, {%8,%9}, {%0,%1,%2,%3};"
        : "+f"(d[0]), "+f"(d[1]), "+f"(d[2]), "+f"(d[3])
        : "r"(a[0]), "r"(a[1]), "r"(a[2]), "r"(a[3]), "r"(b[0]), "r"(b[1]));
}

// ---------------- small kernels ----------------
__global__ void zero_mi_kernel() {
    int i = blockIdx.x * blockDim.x + threadIdx.x;
    g_mi4[i] = make_float4(0.f, 0.f, 0.f, 0.f);
}

// B-fragment generator: for (n, ks, q): {hi(kp0), hi(kp1), lo(kp0), lo(kp1)},
// kp0 = ks*8+q, kp1 = ks*8+4+q, value(kp) = bf16 pair of W[2kp][n], W[2kp+1][n]
__device__ __forceinline__ uint4 make_bfrag(const float* W, int n, int ks, int q,
                                            int kmax, int ldw) {
    int kp0 = ks * 8 + q, kp1 = ks * 8 + 4 + q;
    float a0 = (2 * kp0     < kmax) ? W[(2 * kp0)     * ldw + n] : 0.f;
    float a1 = (2 * kp0 + 1 < kmax) ? W[(2 * kp0 + 1) * ldw + n] : 0.f;
    float b0 = (2 * kp1     < kmax) ? W[(2 * kp1)     * ldw + n] : 0.f;
    float b1 = (2 * kp1 + 1 < kmax) ? W[(2 * kp1 + 1) * ldw + n] : 0.f;
    uint32_t h0, l0, h1, l1;
    split_pack(a0, a1, h0, l0);
    split_pack(b0, b1, h1, l1);
    return make_uint4(h0, h1, l0, l1);
}

__global__ void prep_frag_kernel(const float* __restrict__ W1, const float* __restrict__ W2,
                                 const float* __restrict__ Wn1, const float* __restrict__ Wn2) {
    int i = blockIdx.x * blockDim.x + threadIdx.x;
    if (i < 1024) {                                   // w1: We1[0:24], K padded to 32
        int n = i >> 3, t = i & 7, ks = t >> 2, q = t & 3;
        g_w1f4[i] = make_bfrag(W1, n, ks, q, 24, 128);
    } else if (i < 5120) {                            // w2
        int t2 = i - 1024;
        int n = t2 >> 5, t = t2 & 31, ks = t >> 2, q = t & 3;
        g_w2f4[t2] = make_bfrag(W2, n, ks, q, 128, 128);
    } else if (i < 9216) {                            // wp: We1[24:152]
        int t2 = i - 5120;
        int n = t2 >> 5, t = t2 & 31, ks = t >> 2, q = t & 3;
        g_wpf4[t2] = make_bfrag(W1 + 24 * 128, n, ks, q, 128, 128);
    } else if (i < 13312) {                           // wq: We1[152:280]
        int t2 = i - 9216;
        int n = t2 >> 5, t = t2 & 31, ks = t >> 2, q = t & 3;
        g_wqf4[t2] = make_bfrag(W1 + 152 * 128, n, ks, q, 128, 128);
    } else if (i < 21504) {                           // wn1 (K=256)
        int t2 = i - 13312;
        int n = t2 >> 6, t = t2 & 63, ks = t >> 2, q = t & 3;
        g_wn1f4[t2] = make_bfrag(Wn1, n, ks, q, 256, 128);
    } else if (i < 25600) {                           // wn2
        int t2 = i - 21504;
        int n = t2 >> 5, t = t2 & 31, ks = t >> 2, q = t & 3;
        g_wn2f4[t2] = make_bfrag(Wn2, n, ks, q, 128, 128);
    }
}

// ---------------- A-tile staging: 128 rows x 128 k, row-major fp32 src -> fragment smem ----
// idx = ((rb*8+ks)*8+g)*4+q ; uint4 = {(r,kp),(r+8,kp),(r,kp+4),(r+8,kp+4)}, r=rb*16+g, kp=ks*8+q
__device__ __forceinline__ void stage_tile(const float* __restrict__ src, int n0,
                                           uint4* ahi4, uint4* alo4, int tid) {
    const int rb = tid >> 5, g = (tid >> 2) & 7, q = tid & 3;
    const int r = rb * 16 + g;
    const int gn0 = n0 + r, gn8 = gn0 + 8;
    const bool v0 = gn0 < N_NODES, v8 = gn8 < N_NODES;
    const float2* s0 = (const float2*)src + (size_t)gn0 * 64;
    const float2* s8 = (const float2*)src + (size_t)gn8 * 64;
    const float2 z = make_float2(0.f, 0.f);
#pragma unroll
    for (int ks = 0; ks < 8; ks++) {
        int kp = ks * 8 + q;
        float2 a = v0 ? __ldg(&s0[kp])     : z;
        float2 b = v8 ? __ldg(&s8[kp])     : z;
        float2 c = v0 ? __ldg(&s0[kp + 4]) : z;
        float2 d = v8 ? __ldg(&s8[kp + 4]) : z;
        uint32_t h0, l0, h1, l1, h2, l2, h3, l3;
        split_pack(a.x, a.y, h0, l0);
        split_pack(b.x, b.y, h1, l1);
        split_pack(c.x, c.y, h2, l2);
        split_pack(d.x, d.y, h3, l3);
        int idx = ((rb * 8 + ks) * 8 + g) * 4 + q;
        ahi4[idx] = make_uint4(h0, h1, h2, h3);
        alo4[idx] = make_uint4(l0, l1, l2, l3);
    }
}

// ---------------- pq tensor kernel: P = h @ Wp, Q = h @ Wq (y picks which) ----------------
#define SMEM_PQ 65536

extern "C" __global__ void __launch_bounds__(256, 2)
pq_tensor_kernel(const float* __restrict__ h) {
    extern __shared__ __align__(16) uint4 smf[];
    uint4* ahi4 = smf;
    uint4* alo4 = smf + 2048;

    const int tid = threadIdx.x;
    const int wid = tid >> 5, lane = tid & 31;
    const int g = lane >> 2, q = lane & 3;
    const int wm = wid & 3, wn = wid >> 2;
    const int n0 = blockIdx.x * 128;

    const uint4* wf = (blockIdx.y == 0) ? g_wpf4 : g_wqf4;
    float* outp = (blockIdx.y == 0) ? g_P : g_Q;

    stage_tile(h, n0, ahi4, alo4, tid);
    __syncthreads();

    float acc[2][8][4];
#pragma unroll
    for (int mt = 0; mt < 2; mt++)
#pragma unroll
        for (int nt = 0; nt < 8; nt++)
#pragma unroll
            for (int x = 0; x < 4; x++) acc[mt][nt][x] = 0.f;

#pragma unroll 2
    for (int ks = 0; ks < 8; ks++) {
        uint32_t Ah[2][4], Al[2][4];
#pragma unroll
        for (int mt = 0; mt < 2; mt++) {
            int idx = (((wm * 2 + mt) * 8 + ks) * 8 + g) * 4 + q;
            uint4 vh = ahi4[idx];
            Ah[mt][0] = vh.x; Ah[mt][1] = vh.y; Ah[mt][2] = vh.z; Ah[mt][3] = vh.w;
            uint4 vl = alo4[idx];
            Al[mt][0] = vl.x; Al[mt][1] = vl.y; Al[mt][2] = vl.z; Al[mt][3] = vl.w;
        }
#pragma unroll
        for (int nt = 0; nt < 8; nt++) {
            int n = wn * 64 + nt * 8 + g;
            uint4 w = __ldg(&wf[n * 32 + ks * 4 + q]);
            uint32_t bh[2] = {w.x, w.y};
            uint32_t bl[2] = {w.z, w.w};
#pragma unroll
            for (int mt = 0; mt < 2; mt++) {
                mma_bf16(acc[mt][nt], Ah[mt], bh);
                mma_bf16(acc[mt][nt], Al[mt], bh);
                mma_bf16(acc[mt][nt], Ah[mt], bl);
            }
        }
    }

#pragma unroll
    for (int mt = 0; mt < 2; mt++) {
        int r = wm * 32 + mt * 16 + g;
        int gn0 = n0 + r, gn8 = gn0 + 8;
        bool v0 = gn0 < N_NODES, v8 = gn8 < N_NODES;
#pragma unroll
        for (int nt = 0; nt < 8; nt++) {
            int c = wn * 64 + nt * 8 + q * 2;
            if (v0) *(float2*)&outp[gn0 * 128 + c] = make_float2(acc[mt][nt][0], acc[mt][nt][1]);
            if (v8) *(float2*)&outp[gn8 * 128 + c] = make_float2(acc[mt][nt][2], acc[mt][nt][3]);
        }
    }
}

// ---------------- node tensor kernel ----------------
#define SMEM_NODE 65536

extern "C" __global__ void __launch_bounds__(256, 2)
node_tensor_kernel(const float* __restrict__ h,
                   const float* __restrict__ bn1, const float* __restrict__ bn2,
                   float* __restrict__ out)
{
    extern __shared__ __align__(16) uint4 smf[];
    uint4* ahi4 = smf;
    uint4* alo4 = smf + 2048;

    const int tid = threadIdx.x;
    const int wid = tid >> 5, lane = tid & 31;
    const int g = lane >> 2, q = lane & 3;
    const int wm = wid & 3, wn = wid >> 2;
    const int n0 = blockIdx.x * 128;

    float acc[2][8][4];
#pragma unroll
    for (int mt = 0; mt < 2; mt++)
#pragma unroll
        for (int nt = 0; nt < 8; nt++)
#pragma unroll
            for (int x = 0; x < 4; x++) acc[mt][nt][x] = 0.f;

    // ===== phase 1a: mi part (K rows 0..127 of Wn1) =====
    stage_tile((const float*)g_mi4, n0, ahi4, alo4, tid);
    __syncthreads();
#pragma unroll 2
    for (int ks = 0; ks < 8; ks++) {
        uint32_t Ah[2][4], Al[2][4];
#pragma unroll
        for (int mt = 0; mt < 2; mt++) {
            int idx = (((wm * 2 + mt) * 8 + ks) * 8 + g) * 4 + q;
            uint4 vh = ahi4[idx];
            Ah[mt][0] = vh.x; Ah[mt][1] = vh.y; Ah[mt][2] = vh.z; Ah[mt][3] = vh.w;
            uint4 vl = alo4[idx];
            Al[mt][0] = vl.x; Al[mt][1] = vl.y; Al[mt][2] = vl.z; Al[mt][3] = vl.w;
        }
#pragma unroll
        for (int nt = 0; nt < 8; nt++) {
            int n = wn * 64 + nt * 8 + g;
            uint4 w = __ldg(&g_wn1f4[n * 64 + ks * 4 + q]);
            uint32_t bh[2] = {w.x, w.y};
            uint32_t bl[2] = {w.z, w.w};
#pragma unroll
            for (int mt = 0; mt < 2; mt++) {
                mma_bf16(acc[mt][nt], Ah[mt], bh);
                mma_bf16(acc[mt][nt], Al[mt], bh);
                mma_bf16(acc[mt][nt], Ah[mt], bl);
            }
        }
    }
    __syncthreads();

    // ===== phase 1b: h part (K rows 128..255 of Wn1) =====
    stage_tile(h, n0, ahi4, alo4, tid);
    __syncthreads();
#pragma unroll 2
    for (int ks = 0; ks < 8; ks++) {
        uint32_t Ah[2][4], Al[2][4];
#pragma unroll
        for (int mt = 0; mt < 2; mt++) {
            int idx = (((wm * 2 + mt) * 8 + ks) * 8 + g) * 4 + q;
            uint4 vh = ahi4[idx];
            Ah[mt][0] = vh.x; Ah[mt][1] = vh.y; Ah[mt][2] = vh.z; Ah[mt][3] = vh.w;
            uint4 vl = alo4[idx];
            Al[mt][0] = vl.x; Al[mt][1] = vl.y; Al[mt][2] = vl.z; Al[mt][3] = vl.w;
        }
#pragma unroll
        for (int nt = 0; nt < 8; nt++) {
            int n = wn * 64 + nt * 8 + g;
            uint4 w = __ldg(&g_wn1f4[n * 64 + (ks + 8) * 4 + q]);
            uint32_t bh[2] = {w.x, w.y};
            uint32_t bl[2] = {w.z, w.w};
#pragma unroll
            for (int mt = 0; mt < 2; mt++) {
                mma_bf16(acc[mt][nt], Ah[mt], bh);
                mma_bf16(acc[mt][nt], Al[mt], bh);
                mma_bf16(acc[mt][nt], Ah[mt], bl);
            }
        }
    }
    __syncthreads();

    // ===== epilogue 1: + bn1, relu, split -> fragment smem =====
#pragma unroll
    for (int mt = 0; mt < 2; mt++) {
#pragma unroll
        for (int j = 0; j < 4; j++) {
            uint32_t hi[4], lo[4];
#pragma unroll
            for (int u = 0; u < 2; u++) {
                int nt = 2 * j + u;
                int c = wn * 64 + nt * 8 + q * 2;
                float2 b1v = __ldg((const float2*)&bn1[c]);
                float t0 = fmaxf(acc[mt][nt][0] + b1v.x, 0.f);
                float t1 = fmaxf(acc[mt][nt][1] + b1v.y, 0.f);
                split_pack(t0, t1, hi[2 * u], lo[2 * u]);
                float t2 = fmaxf(acc[mt][nt][2] + b1v.x, 0.f);
                float t3 = fmaxf(acc[mt][nt][3] + b1v.y, 0.f);
                split_pack(t2, t3, hi[2 * u + 1], lo[2 * u + 1]);
            }
            int K8 = wn * 4 + j;
            int idx = (((wm * 2 + mt) * 8 + K8) * 8 + g) * 4 + q;
            ahi4[idx] = make_uint4(hi[0], hi[1], hi[2], hi[3]);
            alo4[idx] = make_uint4(lo[0], lo[1], lo[2], lo[3]);
        }
    }
    __syncthreads();

    // ===== phase 2: @ Wn2 =====
#pragma unroll
    for (int mt = 0; mt < 2; mt++)
#pragma unroll
        for (int nt = 0; nt < 8; nt++)
#pragma unroll
            for (int x = 0; x < 4; x++) acc[mt][nt][x] = 0.f;

#pragma unroll 2
    for (int ks = 0; ks < 8; ks++) {
        uint32_t Ah[2][4], Al[2][4];
#pragma unroll
        for (int mt = 0; mt < 2; mt++) {
            int idx = (((wm * 2 + mt) * 8 + ks) * 8 + g) * 4 + q;
            uint4 vh = ahi4[idx];
            Ah[mt][0] = vh.x; Ah[mt][1] = vh.y; Ah[mt][2] = vh.z; Ah[mt][3] = vh.w;
            uint4 vl = alo4[idx];
            Al[mt][0] = vl.x; Al[mt][1] = vl.y; Al[mt][2] = vl.z; Al[mt][3] = vl.w;
        }
#pragma unroll
        for (int nt = 0; nt < 8; nt++) {
            int n = wn * 64 + nt * 8 + g;
            uint4 w = __ldg(&g_wn2f4[n * 32 + ks * 4 + q]);
            uint32_t bh[2] = {w.x, w.y};
            uint32_t bl[2] = {w.z, w.w};
#pragma unroll
            for (int mt = 0; mt < 2; mt++) {
                mma_bf16(acc[mt][nt], Ah[mt], bh);
                mma_bf16(acc[mt][nt], Al[mt], bh);
                mma_bf16(acc[mt][nt], Ah[mt], bl);
            }
        }
    }

    // ===== epilogue 2: + bn2 -> out =====
#pragma unroll
    for (int mt = 0; mt < 2; mt++) {
        int r = wm * 32 + mt * 16 + g;
        int gn0 = n0 + r, gn8 = gn0 + 8;
        bool v0 = gn0 < N_NODES, v8 = gn8 < N_NODES;
#pragma unroll
        for (int nt = 0; nt < 8; nt++) {
            int c = wn * 64 + nt * 8 + q * 2;
            float2 b2v = __ldg((const float2*)&bn2[c]);
            if (v0) *(float2*)&out[gn0 * 128 + c] =
                make_float2(acc[mt][nt][0] + b2v.x, acc[mt][nt][1] + b2v.y);
            if (v8) *(float2*)&out[gn8 * 128 + c] =
                make_float2(acc[mt][nt][2] + b2v.x, acc[mt][nt][3] + b2v.y);
        }
    }
}

// ---------------- edge kernel (unchanged from R4 — validated) ----------------
#define SMEM_EDGE 67072

extern "C" __global__ void __launch_bounds__(256, 2)
edge_kernel(const int* __restrict__ ei, const float* __restrict__ ea,
            const float* __restrict__ b1, const float* __restrict__ b2,
            const float* __restrict__ Wg, const float* __restrict__ bg)
{
    extern __shared__ __align__(16) char sm[];
    uint4* a2hi4 = (uint4*)sm;
    uint4* a2lo4 = (uint4*)(sm + 32768);
    float* eas   = (float*)sm;            // overlay, phase-1 only
    int*   dsts  = (int*)(sm + 65536);
    int*   srcs  = (int*)(sm + 66048);
    float* gsm   = (float*)(sm + 66560);

    const int tid = threadIdx.x;
    const int wid = tid >> 5, lane = tid & 31;
    const int g = lane >> 2, q = lane & 3;
    const int wm = wid & 3, wn = wid >> 2;
    const int e0 = blockIdx.x * 128;

    if (tid < 128) {
        dsts[tid] = ei[e0 + tid];
        srcs[tid] = ei[N_EDGES + e0 + tid];
        gsm[tid] = 0.f;
    }
    {
        const float4* ea4 = (const float4*)ea;
        for (int i = tid; i < 128 * 6; i += 256) {
            int e = i / 6, j = i % 6;
            *(float4*)&eas[e * 24 + j * 4] = ea4[(e0 + e) * 6 + j];
        }
    }
    __syncthreads();

    float acc[2][8][4];
#pragma unroll
    for (int mt = 0; mt < 2; mt++)
#pragma unroll
        for (int nt = 0; nt < 8; nt++)
#pragma unroll
            for (int x = 0; x < 4; x++) acc[mt][nt][x] = 0.f;

    // ===== phase 1: ea @ W1a (K=24 padded to 32) =====
#pragma unroll
    for (int ks = 0; ks < 2; ks++) {
        uint32_t Ah[2][4], Al[2][4];
#pragma unroll
        for (int mt = 0; mt < 2; mt++) {
            int r = wm * 32 + mt * 16 + g;
            int k0 = ks * 16 + q * 2;
            int k8 = k0 + 8;
            float v00 = eas[r * 24 + k0];
            float v01 = eas[r * 24 + k0 + 1];
            split_pack(v00, v01, Ah[mt][0], Al[mt][0]);
            float v10 = eas[(r + 8) * 24 + k0];
            float v11 = eas[(r + 8) * 24 + k0 + 1];
            split_pack(v10, v11, Ah[mt][1], Al[mt][1]);
            float v20 = (k8 < 24) ? eas[r * 24 + k8] : 0.f;
            float v21 = (k8 < 24) ? eas[r * 24 + k8 + 1] : 0.f;
            split_pack(v20, v21, Ah[mt][2], Al[mt][2]);
            float v30 = (k8 < 24) ? eas[(r + 8) * 24 + k8] : 0.f;
            float v31 = (k8 < 24) ? eas[(r + 8) * 24 + k8 + 1] : 0.f;
            split_pack(v30, v31, Ah[mt][3], Al[mt][3]);
        }
#pragma unroll
        for (int nt = 0; nt < 8; nt++) {
            int n = wn * 64 + nt * 8 + g;
            uint4 w = __ldg(&g_w1f4[n * 8 + ks * 4 + q]);
            uint32_t bh[2] = {w.x, w.y};
            uint32_t bl[2] = {w.z, w.w};
#pragma unroll
            for (int mt = 0; mt < 2; mt++) {
                mma_bf16(acc[mt][nt], Ah[mt], bh);
                mma_bf16(acc[mt][nt], Al[mt], bh);
                mma_bf16(acc[mt][nt], Ah[mt], bl);
            }
        }
    }
    __syncthreads();

    // ===== epilogue 1: + P[dst] + Q[src] + b1, relu, split -> a2 =====
#pragma unroll
    for (int mt = 0; mt < 2; mt++) {
        int r = wm * 32 + mt * 16 + g;
        int d0 = dsts[r], s0 = srcs[r];
        int d8 = dsts[r + 8], s8 = srcs[r + 8];
#pragma unroll
        for (int j = 0; j < 4; j++) {
            uint32_t hi[4], lo[4];
#pragma unroll
            for (int u = 0; u < 2; u++) {
                int nt = 2 * j + u;
                int c = wn * 64 + nt * 8 + q * 2;
                float2 b1v = __ldg((const float2*)&b1[c]);
                float2 pv0 = __ldg((const float2*)&g_P[d0 * 128 + c]);
                float2 qv0 = __ldg((const float2*)&g_Q[s0 * 128 + c]);
                float t0 = fmaxf(acc[mt][nt][0] + pv0.x + qv0.x + b1v.x, 0.f);
                float t1 = fmaxf(acc[mt][nt][1] + pv0.y + qv0.y + b1v.y, 0.f);
                split_pack(t0, t1, hi[2 * u], lo[2 * u]);
                float2 pv8 = __ldg((const float2*)&g_P[d8 * 128 + c]);
                float2 qv8 = __ldg((const float2*)&g_Q[s8 * 128 + c]);
                float t2 = fmaxf(acc[mt][nt][2] + pv8.x + qv8.x + b1v.x, 0.f);
                float t3 = fmaxf(acc[mt][nt][3] + pv8.y + qv8.y + b1v.y, 0.f);
                split_pack(t2, t3, hi[2 * u + 1], lo[2 * u + 1]);
            }
            int K8 = wn * 4 + j;
            int idx = (((wm * 2 + mt) * 8 + K8) * 8 + g) * 4 + q;
            a2hi4[idx] = make_uint4(hi[0], hi[1], hi[2], hi[3]);
            a2lo4[idx] = make_uint4(lo[0], lo[1], lo[2], lo[3]);
        }
    }
    __syncthreads();

    // ===== phase 2: layer2 =====
#pragma unroll
    for (int mt = 0; mt < 2; mt++)
#pragma unroll
        for (int nt = 0; nt < 8; nt++)
#pragma unroll
            for (int x = 0; x < 4; x++) acc[mt][nt][x] = 0.f;

#pragma unroll 2
    for (int ks = 0; ks < 8; ks++) {
        uint32_t Ah[2][4], Al[2][4];
#pragma unroll
        for (int mt = 0; mt < 2; mt++) {
            int idx = (((wm * 2 + mt) * 8 + ks) * 8 + g) * 4 + q;
            uint4 vh = a2hi4[idx];
            Ah[mt][0] = vh.x; Ah[mt][1] = vh.y; Ah[mt][2] = vh.z; Ah[mt][3] = vh.w;
            uint4 vl = a2lo4[idx];
            Al[mt][0] = vl.x; Al[mt][1] = vl.y; Al[mt][2] = vl.z; Al[mt][3] = vl.w;
        }
#pragma unroll
        for (int nt = 0; nt < 8; nt++) {
            int n = wn * 64 + nt * 8 + g;
            uint4 w = __ldg(&g_w2f4[n * 32 + ks * 4 + q]);
            uint32_t bh[2] = {w.x, w.y};
            uint32_t bl[2] = {w.z, w.w};
#pragma unroll
            for (int mt = 0; mt < 2; mt++) {
                mma_bf16(acc[mt][nt], Ah[mt], bh);
                mma_bf16(acc[mt][nt], Al[mt], bh);
                mma_bf16(acc[mt][nt], Ah[mt], bl);
            }
        }
    }

    // ===== epilogue 2: bias + relu -> m (regs); gate partials =====
    {
        float gp[2][2] = {{0.f, 0.f}, {0.f, 0.f}};
#pragma unroll
        for (int mt = 0; mt < 2; mt++)
#pragma unroll
        for (int nt = 0; nt < 8; nt++) {
            int c = wn * 64 + nt * 8 + q * 2;
            float2 b2v = __ldg((const float2*)&b2[c]);
            float2 wgv = __ldg((const float2*)&Wg[c]);
            float m0 = fmaxf(acc[mt][nt][0] + b2v.x, 0.f);
            float m1 = fmaxf(acc[mt][nt][1] + b2v.y, 0.f);
            float m2 = fmaxf(acc[mt][nt][2] + b2v.x, 0.f);
            float m3 = fmaxf(acc[mt][nt][3] + b2v.y, 0.f);
            gp[mt][0] += m0 * wgv.x + m1 * wgv.y;
            gp[mt][1] += m2 * wgv.x + m3 * wgv.y;
            acc[mt][nt][0] = m0; acc[mt][nt][1] = m1;
            acc[mt][nt][2] = m2; acc[mt][nt][3] = m3;
        }
#pragma unroll
        for (int mt = 0; mt < 2; mt++) {
            atomicAdd(&gsm[wm * 32 + mt * 16 + g],     gp[mt][0]);
            atomicAdd(&gsm[wm * 32 + mt * 16 + g + 8], gp[mt][1]);
        }
    }
    __syncthreads();
    if (tid < 128) gsm[tid] = 1.f / (1.f + expf(-(gsm[tid] + __ldg(bg))));
    __syncthreads();

    // ===== scatter: mi[dst] += m * g =====
    {
        float* g_mif = (float*)g_mi4;
#pragma unroll
        for (int mt = 0; mt < 2; mt++) {
            int r = wm * 32 + mt * 16 + g;
            float gg0 = gsm[r], gg1 = gsm[r + 8];
            int d0 = dsts[r], d8 = dsts[r + 8];
#pragma unroll
            for (int nt = 0; nt < 8; nt++) {
                int c = wn * 64 + nt * 8 + q * 2;
                atomicAdd((float2*)&g_mif[d0 * 128 + c],
                          make_float2(acc[mt][nt][0] * gg0, acc[mt][nt][1] * gg0));
                atomicAdd((float2*)&g_mif[d8 * 128 + c],
                          make_float2(acc[mt][nt][2] * gg1, acc[mt][nt][3] * gg1));
            }
        }
    }
}

// ---------------- launch ----------------
extern "C" void kernel_launch(void* const* d_in, const int* in_sizes, int n_in,
                              void* d_out, int out_size)
{
    const float* h   = (const float*)d_in[0];
    const int*   ei  = (const int*)d_in[1];
    const float* ea  = (const float*)d_in[2];
    const float* We1 = (const float*)d_in[3];
    const float* b1  = (const float*)d_in[4];
    const float* We2 = (const float*)d_in[5];
    const float* b2  = (const float*)d_in[6];
    const float* Wg  = (const float*)d_in[7];
    const float* bg  = (const float*)d_in[8];
    const float* Wn1 = (const float*)d_in[9];
    const float* bn1 = (const float*)d_in[10];
    const float* Wn2 = (const float*)d_in[11];
    const float* bn2 = (const float*)d_in[12];
    float* out = (float*)d_out;

    cudaFuncSetAttribute(edge_kernel, cudaFuncAttributeMaxDynamicSharedMemorySize, SMEM_EDGE);
    cudaFuncSetAttribute(pq_tensor_kernel, cudaFuncAttributeMaxDynamicSharedMemorySize, SMEM_PQ);
    cudaFuncSetAttribute(node_tensor_kernel, cudaFuncAttributeMaxDynamicSharedMemorySize, SMEM_NODE);

    const int nblk = (N_NODES + 127) / 128;   // 391
    zero_mi_kernel<<<(N_NODES * (HID / 4)) / 512, 512>>>();
    prep_frag_kernel<<<(25600 + 255) / 256, 256>>>(We1, We2, Wn1, Wn2);
    pq_tensor_kernel<<<dim3(nblk, 2), 256, SMEM_PQ>>>(h);
    edge_kernel<<<N_EDGES / 128, 256, SMEM_EDGE>>>(ei, ea, b1, b2, Wg, bg);
    node_tensor_kernel<<<nblk, 256, SMEM_NODE>>>(h, bn1, bn2, out);
}